// round 10
// baseline (speedup 1.0000x reference)
#include <cuda_runtime.h>
#include <cuda_bf16.h>
#include <cstdint>

#define NMAX 50000
#define EMAX 800000
#define HID 128
#define H 8
#define D 16
#define ALPHA 0.2f
#define BN_EPS 1e-5f

// ---------------- scratch (static device globals; no allocation) ----------------
__device__ float d_h[NMAX * HID];        // post-GEMM features for current layer
__device__ float d_aggb[3][NMAX * HID];  // per-layer normalized aggregation
__device__ float d_esrc[NMAX * H];
__device__ float d_edst[NMAX * H];
__device__ float d_gsum[HID];
__device__ float d_gsq[HID];
__device__ float d_scs[3][HID];          // folded BN scale per layer
__device__ float d_shs[3][HID];          // folded BN shift per layer
__device__ int   d_rowptr[NMAX + 1];     // CSR by dst
__device__ int   d_cursor[NMAX];
__device__ int   d_csrc[EMAX];

__device__ __forceinline__ float eluf(float y) {
    return (y > 0.f) ? y : expm1f(y);
}

// =================================================================================
// GEMM: d_h[n,128] = act(A)[n,128] @ B[128,128], tf32 mma.sync 3-term split.
// mode 0: act = identity; mode 1: act = elu(bn_{b1i}(A1));
// mode 2: act = elu(bn_{b1i}(A1)) + elu(bn_{b2i}(A2))   (skip connection)
// Fragments staged as (k, k+4) uint2 pairs -> LDS.64 reads, conflict-free @ SP=132.
// =================================================================================
__device__ __forceinline__ uint32_t f2tf(float f) {
    uint32_t u;
    asm("cvt.rna.tf32.f32 %0, %1;" : "=r"(u) : "f"(f));
    return u;
}

#define MMA8(c, a, b0, b1)                                                         \
    asm volatile("mma.sync.aligned.m16n8k8.row.col.f32.tf32.tf32.f32 "             \
                 "{%0,%1,%2,%3},{%4,%5,%6,%7},{%8,%9},{%0,%1,%2,%3};"              \
                 : "+f"(c[0]), "+f"(c[1]), "+f"(c[2]), "+f"(c[3])                  \
                 : "r"(a[0]), "r"(a[1]), "r"(a[2]), "r"(a[3]), "r"(b0), "r"(b1))

#define SP 132   // uint2 stride: word-bank = 8*ktid + 2*grp (mod 32) -> conflict-free

__global__ __launch_bounds__(256) void gemm_tc_kernel(const float* __restrict__ A1,
                                                      const float* __restrict__ A2,
                                                      const float* __restrict__ B,
                                                      int n, int mode, int b1i, int b2i) {
    __shared__ uint2 ApH[2][4][SP], ApL[2][4][SP];   // [kk][kp][m] -> (k=8kk+kp, k+4)
    __shared__ uint2 BpH[2][4][SP], BpL[2][4][SP];   // [kk][kp][nn]
    int tid  = threadIdx.x;
    int lane = tid & 31, warp = tid >> 5;
    int wm = warp >> 1, wn = warp & 1;               // warp tile: 32 rows x 64 cols
    int grp = lane >> 2, ktid = lane & 3;
    int row0 = blockIdx.x * 128;

    float acc[2][8][4];
#pragma unroll
    for (int t = 0; t < 2; t++)
#pragma unroll
        for (int j = 0; j < 8; j++)
#pragma unroll
            for (int q = 0; q < 4; q++) acc[t][j][q] = 0.f;

    for (int k0 = 0; k0 < HID; k0 += 16) {
        if (tid < 128) {
            // ---- A stage: one thread = one row, 16 k-cols, fused activation ----
            int ar = tid;
            float fv[16];
            if (row0 + ar < n) {
                const float* ap = &A1[(row0 + ar) * HID + k0];
#pragma unroll
                for (int j = 0; j < 4; j++) {
                    float4 v = *(const float4*)&ap[j * 4];
                    if (mode >= 1) {
                        int c = k0 + j * 4;
                        float4 sc = *(const float4*)&d_scs[b1i][c];
                        float4 sh = *(const float4*)&d_shs[b1i][c];
                        v.x = eluf(fmaf(v.x, sc.x, sh.x));
                        v.y = eluf(fmaf(v.y, sc.y, sh.y));
                        v.z = eluf(fmaf(v.z, sc.z, sh.z));
                        v.w = eluf(fmaf(v.w, sc.w, sh.w));
                        if (mode == 2) {
                            float4 v2  = *(const float4*)&A2[(row0 + ar) * HID + c];
                            float4 sc2 = *(const float4*)&d_scs[b2i][c];
                            float4 sh2 = *(const float4*)&d_shs[b2i][c];
                            v.x += eluf(fmaf(v2.x, sc2.x, sh2.x));
                            v.y += eluf(fmaf(v2.y, sc2.y, sh2.y));
                            v.z += eluf(fmaf(v2.z, sc2.z, sh2.z));
                            v.w += eluf(fmaf(v2.w, sc2.w, sh2.w));
                        }
                    }
                    fv[j * 4 + 0] = v.x; fv[j * 4 + 1] = v.y;
                    fv[j * 4 + 2] = v.z; fv[j * 4 + 3] = v.w;
                }
            } else {
#pragma unroll
                for (int q = 0; q < 16; q++) fv[q] = 0.f;
            }
#pragma unroll
            for (int kk = 0; kk < 2; kk++)
#pragma unroll
                for (int kp = 0; kp < 4; kp++) {
                    float v1 = fv[kk * 8 + kp], v2 = fv[kk * 8 + kp + 4];
                    uint32_t h1 = f2tf(v1), h2 = f2tf(v2);
                    uint32_t l1 = f2tf(v1 - __uint_as_float(h1));
                    uint32_t l2 = f2tf(v2 - __uint_as_float(h2));
                    ApH[kk][kp][ar] = make_uint2(h1, h2);
                    ApL[kk][kp][ar] = make_uint2(l1, l2);
                }
        } else {
            // ---- B stage: thread = (k-pair row, 8 strided cols) ----
            int t2 = tid - 128;
            int colg = t2 & 15, rowp = t2 >> 4;
            int kk = rowp >> 2, kp = rowp & 3;
            const float* b1p = &B[(k0 + kk * 8 + kp) * HID];
            const float* b2p = b1p + 4 * HID;
#pragma unroll
            for (int c = 0; c < 8; c++) {
                int col = colg + c * 16;
                float v1 = __ldg(&b1p[col]);
                float v2 = __ldg(&b2p[col]);
                uint32_t h1 = f2tf(v1), h2 = f2tf(v2);
                uint32_t l1 = f2tf(v1 - __uint_as_float(h1));
                uint32_t l2 = f2tf(v2 - __uint_as_float(h2));
                BpH[kk][kp][col] = make_uint2(h1, h2);
                BpL[kk][kp][col] = make_uint2(l1, l2);
            }
        }
        __syncthreads();

#pragma unroll
        for (int kk = 0; kk < 2; kk++) {
            uint32_t ah[2][4], al[2][4];
#pragma unroll
            for (int t = 0; t < 2; t++) {
                int m = wm * 32 + t * 16 + grp;
                uint2 pm  = ApH[kk][ktid][m];
                uint2 pm8 = ApH[kk][ktid][m + 8];
                ah[t][0] = pm.x;  ah[t][1] = pm8.x;
                ah[t][2] = pm.y;  ah[t][3] = pm8.y;
                uint2 qm  = ApL[kk][ktid][m];
                uint2 qm8 = ApL[kk][ktid][m + 8];
                al[t][0] = qm.x;  al[t][1] = qm8.x;
                al[t][2] = qm.y;  al[t][3] = qm8.y;
            }
#pragma unroll
            for (int j = 0; j < 8; j++) {
                int nn = wn * 64 + j * 8 + grp;
                uint2 bh = BpH[kk][ktid][nn];
                uint2 bl = BpL[kk][ktid][nn];
#pragma unroll
                for (int t = 0; t < 2; t++) {
                    MMA8(acc[t][j], ah[t], bh.x, bh.y);   // hi*hi
                    MMA8(acc[t][j], ah[t], bl.x, bl.y);   // hi*lo
                    MMA8(acc[t][j], al[t], bh.x, bh.y);   // lo*hi
                }
            }
        }
        __syncthreads();
    }

#pragma unroll
    for (int t = 0; t < 2; t++) {
        int r0 = row0 + wm * 32 + t * 16 + grp;
#pragma unroll
        for (int j = 0; j < 8; j++) {
            int c = wn * 64 + j * 8 + ktid * 2;
            if (r0 < n)
                *(float2*)&d_h[r0 * HID + c] = make_float2(acc[t][j][0], acc[t][j][1]);
            if (r0 + 8 < n)
                *(float2*)&d_h[(r0 + 8) * HID + c] = make_float2(acc[t][j][2], acc[t][j][3]);
        }
    }
}

// ---------------- attention coefficients + BN-stat reset -------------------------
__global__ void attn_kernel(const float* __restrict__ a, int n) {
    int t = blockIdx.x * blockDim.x + threadIdx.x;
    if (t < HID) { d_gsum[t] = 0.f; d_gsq[t] = 0.f; }
    if (t >= n * H) return;
    int node = t >> 3, head = t & 7;
    const float4* hp = (const float4*)(d_h + node * HID + head * D);
    const float4* ap = (const float4*)(a + head * 2 * D);
    float s1 = 0.f, s2 = 0.f;
#pragma unroll
    for (int i = 0; i < 4; i++) {
        float4 hv = hp[i];
        float4 a1v = __ldg(&ap[i]);
        float4 a2v = __ldg(&ap[4 + i]);
        s1 = fmaf(hv.x, a1v.x, fmaf(hv.y, a1v.y, fmaf(hv.z, a1v.z, fmaf(hv.w, a1v.w, s1))));
        s2 = fmaf(hv.x, a2v.x, fmaf(hv.y, a2v.y, fmaf(hv.z, a2v.z, fmaf(hv.w, a2v.w, s2))));
    }
    d_esrc[t] = s1;
    d_edst[t] = s2;
}

// ---------------- CSR construction (once per launch) -----------------------------
__global__ void hist_kernel(const int* __restrict__ ei, int e) {
    int t = blockIdx.x * blockDim.x + threadIdx.x;
    if (t < e) atomicAdd(&d_cursor[__ldg(&ei[e + t])], 1);
}

__global__ void scan_kernel(int n) {
    __shared__ int wsum[32];
    int tid = threadIdx.x;                 // 1024 threads, 1 block
    int lane = tid & 31, wid = tid >> 5;
    int chunk = (n + 1023) / 1024;
    int lo = tid * chunk;
    int hi = min(lo + chunk, n);
    int s = 0;
    for (int i = lo; i < hi; i++) s += d_cursor[i];
    int inc = s;
#pragma unroll
    for (int o = 1; o < 32; o <<= 1) {
        int v = __shfl_up_sync(~0u, inc, o);
        if (lane >= o) inc += v;
    }
    if (lane == 31) wsum[wid] = inc;
    __syncthreads();
    if (wid == 0) {
        int v = wsum[lane];
        int iv = v;
#pragma unroll
        for (int o = 1; o < 32; o <<= 1) {
            int u = __shfl_up_sync(~0u, iv, o);
            if (lane >= o) iv += u;
        }
        wsum[lane] = iv - v;
    }
    __syncthreads();
    int off = wsum[wid] + inc - s;
    for (int i = lo; i < hi; i++) {
        int c = d_cursor[i];
        d_rowptr[i] = off;
        d_cursor[i] = off;
        off += c;
    }
    if (hi == n) d_rowptr[n] = off;
}

__global__ void scatter_kernel(const int* __restrict__ ei, int e) {
    int t = blockIdx.x * blockDim.x + threadIdx.x;
    if (t >= e) return;
    int dst = __ldg(&ei[e + t]);
    int pos = atomicAdd(&d_cursor[dst], 1);
    d_csrc[pos] = __ldg(&ei[t]);
}

// ---------------- fused GAT aggregation: one warp per dst node -------------------
// Single pass (no softmax max: ratio is shift-invariant, exp finite here).
// Unroll-4: batch index loads, then 4 independent esrc + 4 independent h gathers.
__global__ __launch_bounds__(256) void agg_kernel(float* __restrict__ aggout, int n) {
    __shared__ float rsum[8][HID];
    int wid = threadIdx.x >> 5, lane = threadIdx.x & 31;
    int w = blockIdx.x * 8 + wid;
    int head = lane >> 2;
    float4 o = make_float4(0.f, 0.f, 0.f, 0.f);

    if (w < n) {
        int start = d_rowptr[w], end = d_rowptr[w + 1];
        float ed = d_edst[w * H + head];
        float4 acc = make_float4(0.f, 0.f, 0.f, 0.f);
        float den = 0.f;
        int i = start;
        for (; i + 4 <= end; i += 4) {
            int s0 = __ldg(&d_csrc[i]);
            int s1 = __ldg(&d_csrc[i + 1]);
            int s2 = __ldg(&d_csrc[i + 2]);
            int s3 = __ldg(&d_csrc[i + 3]);
            float e0 = d_esrc[s0 * H + head] + ed;
            float e1 = d_esrc[s1 * H + head] + ed;
            float e2 = d_esrc[s2 * H + head] + ed;
            float e3 = d_esrc[s3 * H + head] + ed;
            float4 h0 = *(const float4*)&d_h[s0 * HID + lane * 4];
            float4 h1 = *(const float4*)&d_h[s1 * HID + lane * 4];
            float4 h2 = *(const float4*)&d_h[s2 * HID + lane * 4];
            float4 h3 = *(const float4*)&d_h[s3 * HID + lane * 4];
            e0 = (e0 >= 0.f) ? e0 : ALPHA * e0;
            e1 = (e1 >= 0.f) ? e1 : ALPHA * e1;
            e2 = (e2 >= 0.f) ? e2 : ALPHA * e2;
            e3 = (e3 >= 0.f) ? e3 : ALPHA * e3;
            float w0 = __expf(e0), w1 = __expf(e1);
            float w2 = __expf(e2), w3 = __expf(e3);
            acc.x = fmaf(h0.x, w0, fmaf(h1.x, w1, fmaf(h2.x, w2, fmaf(h3.x, w3, acc.x))));
            acc.y = fmaf(h0.y, w0, fmaf(h1.y, w1, fmaf(h2.y, w2, fmaf(h3.y, w3, acc.y))));
            acc.z = fmaf(h0.z, w0, fmaf(h1.z, w1, fmaf(h2.z, w2, fmaf(h3.z, w3, acc.z))));
            acc.w = fmaf(h0.w, w0, fmaf(h1.w, w1, fmaf(h2.w, w2, fmaf(h3.w, w3, acc.w))));
            den += (w0 + w1) + (w2 + w3);
        }
        for (; i < end; i++) {
            int s0 = __ldg(&d_csrc[i]);
            float e0 = d_esrc[s0 * H + head] + ed;
            float4 h0 = *(const float4*)&d_h[s0 * HID + lane * 4];
            e0 = (e0 >= 0.f) ? e0 : ALPHA * e0;
            float w0 = __expf(e0);
            acc.x = fmaf(h0.x, w0, acc.x);
            acc.y = fmaf(h0.y, w0, acc.y);
            acc.z = fmaf(h0.z, w0, acc.z);
            acc.w = fmaf(h0.w, w0, acc.w);
            den += w0;
        }
        float inv = 1.f / (den + 1e-16f);
        o = make_float4(acc.x * inv, acc.y * inv, acc.z * inv, acc.w * inv);
        *(float4*)&aggout[w * HID + lane * 4] = o;
    }

    // per-block BN stat reduction (zeros from inactive warps are harmless)
    *(float4*)&rsum[wid][lane * 4] = o;
    __syncthreads();
    if (threadIdx.x < HID) {
        int c = threadIdx.x;
        float s = 0.f, q = 0.f;
#pragma unroll
        for (int k = 0; k < 8; k++) {
            float v = rsum[k][c];
            s += v;
            q = fmaf(v, v, q);
        }
        atomicAdd(&d_gsum[c], s);
        atomicAdd(&d_gsq[c], q);
    }
}

// ---------------- fold BN stats into per-channel scale/shift ---------------------
__global__ void bnpar_kernel(const float* __restrict__ g, const float* __restrict__ b,
                             int idx, float invn) {
    int c = threadIdx.x;
    float mu = d_gsum[c] * invn;
    float var = d_gsq[c] * invn - mu * mu;
    float sc = g[c] * rsqrtf(var + BN_EPS);
    d_scs[idx][c] = sc;
    d_shs[idx][c] = b[c] - mu * sc;
}

// ---------------- final output: out = bn3(agg3) ----------------------------------
__global__ void out_kernel(const float* __restrict__ agg, float* __restrict__ out, int n) {
    int t = blockIdx.x * blockDim.x + threadIdx.x;
    if (t >= n * (HID / 4)) return;
    float4 v  = ((const float4*)agg)[t];
    int c = (t * 4) & (HID - 1);
    float4 sc = *(const float4*)&d_scs[2][c];
    float4 sh = *(const float4*)&d_shs[2][c];
    ((float4*)out)[t] = make_float4(fmaf(v.x, sc.x, sh.x), fmaf(v.y, sc.y, sh.y),
                                    fmaf(v.z, sc.z, sh.z), fmaf(v.w, sc.w, sh.w));
}

// ---------------- host-side driver -----------------------------------------------
extern "C" void kernel_launch(void* const* d_in, const int* in_sizes, int n_in,
                              void* d_out, int out_size) {
    const float* x  = (const float*)d_in[0];
    const int*   ei = (const int*)  d_in[1];
    const float* W1 = (const float*)d_in[2];
    const float* a1 = (const float*)d_in[3];
    const float* W2 = (const float*)d_in[4];
    const float* a2 = (const float*)d_in[5];
    const float* W3 = (const float*)d_in[6];
    const float* a3 = (const float*)d_in[7];
    const float* g1 = (const float*)d_in[8];
    const float* b1 = (const float*)d_in[9];
    const float* g2 = (const float*)d_in[10];
    const float* b2 = (const float*)d_in[11];
    const float* g3 = (const float*)d_in[12];
    const float* b3 = (const float*)d_in[13];

    int n = in_sizes[0] / HID;
    int e = in_sizes[1] / 2;
    float invn = 1.f / (float)n;

    float* aggbase = nullptr;
    void* curp = nullptr;
    cudaGetSymbolAddress((void**)&aggbase, d_aggb);
    cudaGetSymbolAddress(&curp, d_cursor);
    float* agg1 = aggbase;
    float* agg2 = aggbase + (size_t)NMAX * HID;
    float* agg3 = aggbase + (size_t)2 * NMAX * HID;

    // ---- build dst-CSR once; reused by all 3 layers ----
    cudaMemsetAsync(curp, 0, n * sizeof(int));
    hist_kernel<<<(e + 255) / 256, 256>>>(ei, e);
    scan_kernel<<<1, 1024>>>(n);
    scatter_kernel<<<(e + 255) / 256, 256>>>(ei, e);

    int gblk = (n + 127) / 128;
    int ablk = (n * H + 255) / 256;
    int wblk = (n + 7) / 8;

    // layer 1
    gemm_tc_kernel<<<gblk, 256>>>(x, nullptr, W1, n, 0, 0, 0);
    attn_kernel<<<ablk, 256>>>(a1, n);
    agg_kernel<<<wblk, 256>>>(agg1, n);
    bnpar_kernel<<<1, HID>>>(g1, b1, 0, invn);
    // layer 2 (input = elu(bn1(agg1)) computed in GEMM loader)
    gemm_tc_kernel<<<gblk, 256>>>(agg1, nullptr, W2, n, 1, 0, 0);
    attn_kernel<<<ablk, 256>>>(a2, n);
    agg_kernel<<<wblk, 256>>>(agg2, n);
    bnpar_kernel<<<1, HID>>>(g2, b2, 1, invn);
    // layer 3 (input = elu(bn1(agg1)) + elu(bn2(agg2)) in GEMM loader)
    gemm_tc_kernel<<<gblk, 256>>>(agg1, agg2, W3, n, 2, 0, 1);
    attn_kernel<<<ablk, 256>>>(a3, n);
    agg_kernel<<<wblk, 256>>>(agg3, n);
    bnpar_kernel<<<1, HID>>>(g3, b3, 2, invn);
    out_kernel<<<(n * (HID / 4) + 255) / 256, 256>>>(agg3, (float*)d_out, n);
}